// round 8
// baseline (speedup 1.0000x reference)
#include <cuda_runtime.h>
#include <cuda_fp16.h>
#include <cstdint>

#define T_TOK 4096
#define HID   2048
#define QD    2048
#define INTER_N 10944

// ---------------- scratch (__device__ globals; no allocs allowed) ----------------
__device__ __half g_w16q[(size_t)QD * HID];
__device__ __half g_w16o[(size_t)HID * QD];
__device__ __half g_w16g[(size_t)INTER_N * HID];
__device__ __half g_w16u[(size_t)INTER_N * HID];
__device__ __half g_w16d[(size_t)HID * INTER_N];
__device__ __half g_a16h[(size_t)T_TOK * HID];     // rmsnorm(x) fp16
__device__ __half g_a16q[(size_t)T_TOK * QD];      // q fp16
__device__ __half g_a16p[(size_t)T_TOK * HID];     // rmsnorm(hidden) fp16
__device__ __half g_a16m[(size_t)T_TOK * INTER_N]; // silu(gate)*up fp16
__device__ float g_hidden[(size_t)T_TOK * HID];
__device__ float g_prodf[(size_t)T_TOK * INTER_N]; // silu(gate) fp32

// ---------------- PTX helpers ----------------
__device__ __forceinline__ uint32_t smem_u32(const void* p) {
    uint32_t a;
    asm("{ .reg .u64 t; cvta.to.shared.u64 t, %1; cvt.u32.u64 %0, t; }" : "=r"(a) : "l"(p));
    return a;
}
#define CP16(dst, src)   asm volatile("cp.async.cg.shared.global [%0], [%1], 16;" :: "r"(dst), "l"(src) : "memory")
#define CP_COMMIT()      asm volatile("cp.async.commit_group;" ::: "memory")
#define CP_WAIT2()       asm volatile("cp.async.wait_group 2;" ::: "memory")

__device__ __forceinline__ void ldm_x4(uint32_t* r, uint32_t addr) {
    asm volatile("ldmatrix.sync.aligned.m8n8.x4.shared.b16 {%0,%1,%2,%3}, [%4];"
                 : "=r"(r[0]), "=r"(r[1]), "=r"(r[2]), "=r"(r[3]) : "r"(addr));
}
__device__ __forceinline__ void mma_fp16(float* c, const uint32_t* a, const uint32_t* b) {
    asm volatile(
        "mma.sync.aligned.m16n8k16.row.col.f32.f16.f16.f32 "
        "{%0,%1,%2,%3}, {%4,%5,%6,%7}, {%8,%9}, {%0,%1,%2,%3};"
        : "+f"(c[0]), "+f"(c[1]), "+f"(c[2]), "+f"(c[3])
        : "r"(a[0]), "r"(a[1]), "r"(a[2]), "r"(a[3]), "r"(b[0]), "r"(b[1]));
}

// ---------------- weight convert: fp32 -> fp16 (8 elems/thread/iter) ----------------
__global__ void cvt_w_kernel(const float4* __restrict__ W, uint4* __restrict__ O,
                             unsigned total8) {
    unsigned i = blockIdx.x * blockDim.x + threadIdx.x;
    const unsigned stride = gridDim.x * blockDim.x;
    for (; i < total8; i += stride) {
        float4 v0 = W[i * 2];
        float4 v1 = W[i * 2 + 1];
        __half2 h0 = __floats2half2_rn(v0.x, v0.y);
        __half2 h1 = __floats2half2_rn(v0.z, v0.w);
        __half2 h2 = __floats2half2_rn(v1.x, v1.y);
        __half2 h3 = __floats2half2_rn(v1.z, v1.w);
        uint4 o;
        o.x = *(uint32_t*)&h0; o.y = *(uint32_t*)&h1;
        o.z = *(uint32_t*)&h2; o.w = *(uint32_t*)&h3;
        O[i] = o;
    }
}

// ---------------- RMSNorm -> fp16 ----------------
__global__ void rmsnorm_f16_kernel(const float* __restrict__ x,
                                   const float* __restrict__ w,
                                   __half* __restrict__ out) {
    const int row = blockIdx.x;
    const float4* xr = (const float4*)(x + (size_t)row * HID);
    const float4* wv4 = (const float4*)w;

    float4 v[2];
    float ss = 0.f;
#pragma unroll
    for (int i = 0; i < 2; i++) {
        v[i] = xr[threadIdx.x + i * 256];
        ss += v[i].x * v[i].x + v[i].y * v[i].y + v[i].z * v[i].z + v[i].w * v[i].w;
    }
#pragma unroll
    for (int o = 16; o; o >>= 1) ss += __shfl_xor_sync(0xffffffffu, ss, o);
    __shared__ float sred[8];
    if ((threadIdx.x & 31) == 0) sred[threadIdx.x >> 5] = ss;
    __syncthreads();
    if (threadIdx.x < 8) {
        float t = sred[threadIdx.x];
#pragma unroll
        for (int o = 4; o; o >>= 1) t += __shfl_xor_sync(0xffu, t, o);
        if (threadIdx.x == 0) sred[0] = t;
    }
    __syncthreads();
    const float scale = rsqrtf(sred[0] * (1.0f / HID) + 1e-6f);

    uint2* orow = (uint2*)(out + (size_t)row * HID);
#pragma unroll
    for (int i = 0; i < 2; i++) {
        float4 wv = wv4[threadIdx.x + i * 256];
        __half2 h01 = __floats2half2_rn(v[i].x * scale * wv.x, v[i].y * scale * wv.y);
        __half2 h23 = __floats2half2_rn(v[i].z * scale * wv.z, v[i].w * scale * wv.w);
        uint2 o;
        o.x = *(uint32_t*)&h01;
        o.y = *(uint32_t*)&h23;
        orow[threadIdx.x + i * 256] = o;
    }
}

// ---------------- HMMA GEMM: C[m,n] = epi(sum_k A[m,k]*B[n,k]), fp16 ----------------
// CTA tile 128x256, warp tile 64x64 (2m x 4n warps), BK=64, 4-stage cp.async.
// A: [4096][K] fp16, B: [N][K] fp16, SW128 swizzle, ldmatrix + mma.m16n8k16.
// EPI: 1 = silu->C(f32) ; 2 = acc*C -> Dst(f16) ; 3 = acc+Res -> C(f32) ; 4 = Dst(f16)
#define NSTAGE 4
#define A_BYTES 16384               // 128 rows * 128B
#define B_BYTES 32768               // 256 rows * 128B
#define STG     (A_BYTES + B_BYTES) // 48KB
#define SMEM_TOTAL (NSTAGE * STG)   // 192KB

template <int EPI>
__global__ void __launch_bounds__(256, 1)
gemm_f16(const __half* __restrict__ A, const __half* __restrict__ B,
         float* __restrict__ C, const float* __restrict__ Res,
         __half* __restrict__ Dst, int N, int K) {
    extern __shared__ __align__(1024) char smem[];
    const uint32_t sb = smem_u32(smem);
    const int tid = threadIdx.x;
    const int lane = tid & 31;
    const int w = tid >> 5;
    const int mw = w >> 2;            // 0..1  (64-row slab)
    const int nw = w & 3;             // 0..3  (64-col slab)
    const int bm = blockIdx.y * 128;
    const int bn = blockIdx.x * 256;
    const int nch = K >> 6;           // 64-elem chunks
    const uint32_t strideK = (uint32_t)K;

    // ---- loader precompute: A 4 x 16B, B 8 x 16B per thread ----
    const char* Abase = (const char*)A;
    const char* Bbase = (const char*)B;
    uint32_t a_dst[4], a_off[4], b_dst[8], b_off[8];
#pragma unroll
    for (int i = 0; i < 4; i++) {
        int idx = tid + 256 * i, r = idx >> 3, c = idx & 7;
        a_dst[i] = (uint32_t)(r * 128 + ((c * 16) ^ ((r & 7) << 4)));
        a_off[i] = ((uint32_t)(bm + r) * strideK + (uint32_t)c * 8u) * 2u;
    }
#pragma unroll
    for (int i = 0; i < 8; i++) {
        int idx = tid + 256 * i, r = idx >> 3, c = idx & 7;
        int gr = bn + r; if (gr > N - 1) gr = N - 1;
        b_dst[i] = (uint32_t)(r * 128 + ((c * 16) ^ ((r & 7) << 4)));
        b_off[i] = ((uint32_t)gr * strideK + (uint32_t)c * 8u) * 2u;
    }

    auto load_stage = [&](int stage, int ch) {
        uint32_t ab = sb + stage * STG;
        uint32_t bb = ab + A_BYTES;
        uint32_t co = (uint32_t)ch * 128u;           // 64 halfs = 128 bytes
#pragma unroll
        for (int i = 0; i < 4; i++) CP16(ab + a_dst[i], Abase + a_off[i] + co);
#pragma unroll
        for (int i = 0; i < 8; i++) CP16(bb + b_dst[i], Bbase + b_off[i] + co);
        CP_COMMIT();
    };

    // ---- ldmatrix lane addressing ----
    const int arow = mw * 64 + (lane & 15);
    const uint32_t a_xor = (uint32_t)((arow & 7) << 4);
    const uint32_t a_rb = (uint32_t)(arow * 128);
    const uint32_t a_k0 = (uint32_t)((lane >> 4) * 16);
    const int brow = nw * 64 + ((lane >> 4) & 1) * 8 + (lane & 7);
    const uint32_t b_xor = (uint32_t)((brow & 7) << 4);
    const uint32_t b_rb = (uint32_t)(brow * 128);
    const uint32_t b_k0 = (uint32_t)(((lane >> 3) & 1) * 16);

    float acc[4][8][4];
#pragma unroll
    for (int i = 0; i < 4; i++)
#pragma unroll
        for (int j = 0; j < 8; j++)
#pragma unroll
            for (int q = 0; q < 4; q++) acc[i][j][q] = 0.f;

    // ---- pipeline: 3-deep prefetch over 4 stages ----
    load_stage(0, 0);
    load_stage(1, 1);
    load_stage(2, 2);

    for (int s = 0; s < nch; s++) {
        const int stage = s & 3;
        CP_WAIT2();                   // chunk s resident
        __syncthreads();              // all warps done with stage (s-1)&3

        const int nc = s + 3;
        if (nc < nch) load_stage(nc & 3, nc);
        else          CP_COMMIT();    // empty group keeps wait accounting exact

        const uint32_t sA = sb + stage * STG;
        const uint32_t sB = sA + A_BYTES;
#pragma unroll
        for (int kk = 0; kk < 4; kk++) {
            uint32_t af[4][4], bf[4][4];
#pragma unroll
            for (int ma = 0; ma < 4; ma++)
                ldm_x4(af[ma], sA + a_rb + (uint32_t)(ma * 2048) + ((kk * 32 + a_k0) ^ a_xor));
#pragma unroll
            for (int nb = 0; nb < 4; nb++)
                ldm_x4(bf[nb], sB + b_rb + (uint32_t)(nb * 2048) + ((kk * 32 + b_k0) ^ b_xor));
#pragma unroll
            for (int ma = 0; ma < 4; ma++)
#pragma unroll
                for (int na = 0; na < 8; na++)
                    mma_fp16(acc[ma][na], af[ma], &bf[na >> 1][(na & 1) * 2]);
        }
    }

    // ---- epilogue ----
#pragma unroll
    for (int ma = 0; ma < 4; ma++) {
        const int gm0 = bm + mw * 64 + ma * 16 + (lane >> 2);
#pragma unroll
        for (int na = 0; na < 8; na++) {
            const int gn = bn + nw * 64 + na * 8 + (lane & 3) * 2;
            if (gn >= N) continue;
            const float* c = acc[ma][na];
#pragma unroll
            for (int h = 0; h < 2; h++) {
                const int gm = gm0 + h * 8;
                float v0 = c[h * 2 + 0], v1 = c[h * 2 + 1];
                if (EPI == 1) {
                    float2 o;
                    o.x = v0 / (1.f + __expf(-v0));
                    o.y = v1 / (1.f + __expf(-v1));
                    *(float2*)(C + (size_t)gm * N + gn) = o;
                } else if (EPI == 2) {
                    float2 g = *(const float2*)(C + (size_t)gm * N + gn);
                    __half2 o = __floats2half2_rn(v0 * g.x, v1 * g.y);
                    *(__half2*)(Dst + (size_t)gm * N + gn) = o;
                } else if (EPI == 3) {
                    float2 rr = *(const float2*)(Res + (size_t)gm * N + gn);
                    float2 o; o.x = v0 + rr.x; o.y = v1 + rr.y;
                    *(float2*)(C + (size_t)gm * N + gn) = o;
                } else {  // EPI == 4
                    __half2 o = __floats2half2_rn(v0, v1);
                    *(__half2*)(Dst + (size_t)gm * N + gn) = o;
                }
            }
        }
    }
}

// ---------------- launch ----------------
extern "C" void kernel_launch(void* const* d_in, const int* in_sizes, int n_in,
                              void* d_out, int out_size) {
    const float* x      = (const float*)d_in[0];
    const float* in_w   = (const float*)d_in[2];
    const float* post_w = (const float*)d_in[3];
    const float* Wq     = (const float*)d_in[4];
    const float* Wo     = (const float*)d_in[5];
    const float* Wg     = (const float*)d_in[6];
    const float* Wu     = (const float*)d_in[7];
    const float* Wd     = (const float*)d_in[8];
    float* out = (float*)d_out;

    __half *w16q, *w16o, *w16g, *w16u, *w16d, *a16h, *a16q, *a16p, *a16m;
    float *hidden, *prodf;
    cudaGetSymbolAddress((void**)&w16q, g_w16q);
    cudaGetSymbolAddress((void**)&w16o, g_w16o);
    cudaGetSymbolAddress((void**)&w16g, g_w16g);
    cudaGetSymbolAddress((void**)&w16u, g_w16u);
    cudaGetSymbolAddress((void**)&w16d, g_w16d);
    cudaGetSymbolAddress((void**)&a16h, g_a16h);
    cudaGetSymbolAddress((void**)&a16q, g_a16q);
    cudaGetSymbolAddress((void**)&a16p, g_a16p);
    cudaGetSymbolAddress((void**)&a16m, g_a16m);
    cudaGetSymbolAddress((void**)&hidden, g_hidden);
    cudaGetSymbolAddress((void**)&prodf, g_prodf);

    cudaFuncSetAttribute(gemm_f16<1>, cudaFuncAttributeMaxDynamicSharedMemorySize, SMEM_TOTAL);
    cudaFuncSetAttribute(gemm_f16<2>, cudaFuncAttributeMaxDynamicSharedMemorySize, SMEM_TOTAL);
    cudaFuncSetAttribute(gemm_f16<3>, cudaFuncAttributeMaxDynamicSharedMemorySize, SMEM_TOTAL);
    cudaFuncSetAttribute(gemm_f16<4>, cudaFuncAttributeMaxDynamicSharedMemorySize, SMEM_TOTAL);

    // weight converts (fp32 -> fp16)
    cvt_w_kernel<<<2048, 256>>>((const float4*)Wq, (uint4*)w16q, (unsigned)((size_t)QD * HID / 8));
    cvt_w_kernel<<<2048, 256>>>((const float4*)Wo, (uint4*)w16o, (unsigned)((size_t)HID * QD / 8));
    cvt_w_kernel<<<2048, 256>>>((const float4*)Wg, (uint4*)w16g, (unsigned)((size_t)INTER_N * HID / 8));
    cvt_w_kernel<<<2048, 256>>>((const float4*)Wu, (uint4*)w16u, (unsigned)((size_t)INTER_N * HID / 8));
    cvt_w_kernel<<<2048, 256>>>((const float4*)Wd, (uint4*)w16d, (unsigned)((size_t)HID * INTER_N / 8));

    const int MT = T_TOK / 128;  // 32

    // 1. input_layernorm -> fp16
    rmsnorm_f16_kernel<<<T_TOK, 256>>>(x, in_w, a16h);
    // 2. q = hnorm @ Wq^T -> fp16
    gemm_f16<4><<<dim3((QD + 255) / 256, MT), 256, SMEM_TOTAL>>>(a16h, w16q, nullptr, nullptr, a16q, QD, HID);
    // 3. hidden = x + q @ Wo^T
    gemm_f16<3><<<dim3((HID + 255) / 256, MT), 256, SMEM_TOTAL>>>(a16q, w16o, hidden, x, nullptr, HID, QD);
    // 4. post_attention_layernorm -> fp16
    rmsnorm_f16_kernel<<<T_TOK, 256>>>(hidden, post_w, a16p);
    // 5. prodf = silu(hpost @ Wg^T)  (fp32)
    gemm_f16<1><<<dim3((INTER_N + 255) / 256, MT), 256, SMEM_TOTAL>>>(a16p, w16g, prodf, nullptr, nullptr, INTER_N, HID);
    // 6. a16m = fp16(prodf * (hpost @ Wu^T))
    gemm_f16<2><<<dim3((INTER_N + 255) / 256, MT), 256, SMEM_TOTAL>>>(a16p, w16u, prodf, nullptr, a16m, INTER_N, HID);
    // 7. out = hidden + a16m @ Wd^T
    gemm_f16<3><<<dim3((HID + 255) / 256, MT), 256, SMEM_TOTAL>>>(a16m, w16d, out, hidden, nullptr, HID, INTER_N);
}

// round 9
// speedup vs baseline: 1.1164x; 1.1164x over previous
#include <cuda_runtime.h>
#include <cuda_fp16.h>
#include <cstdint>

#define T_TOK 4096
#define HID   2048
#define QD    2048
#define INTER_N 10944

// ---------------- scratch (__device__ globals; no allocs allowed) ----------------
__device__ __half g_w16q[(size_t)QD * HID];
__device__ __half g_w16o[(size_t)HID * QD];
__device__ __half g_w16g[(size_t)INTER_N * HID];
__device__ __half g_w16u[(size_t)INTER_N * HID];
__device__ __half g_w16d[(size_t)HID * INTER_N];
__device__ __half g_a16h[(size_t)T_TOK * HID];     // rmsnorm(x) fp16
__device__ __half g_a16q[(size_t)T_TOK * QD];      // q fp16
__device__ __half g_a16p[(size_t)T_TOK * HID];     // rmsnorm(hidden) fp16
__device__ __half g_a16m[(size_t)T_TOK * INTER_N]; // silu(gate)*up fp16
__device__ float g_hidden[(size_t)T_TOK * HID];
__device__ float g_prodf[(size_t)T_TOK * INTER_N]; // silu(gate) fp32

// ---------------- PTX helpers ----------------
__device__ __forceinline__ uint32_t smem_u32(const void* p) {
    uint32_t a;
    asm("{ .reg .u64 t; cvta.to.shared.u64 t, %1; cvt.u32.u64 %0, t; }" : "=r"(a) : "l"(p));
    return a;
}
#define CP16(dst, src)   asm volatile("cp.async.cg.shared.global [%0], [%1], 16;" :: "r"(dst), "l"(src) : "memory")
#define CP_COMMIT()      asm volatile("cp.async.commit_group;" ::: "memory")
#define CP_WAIT1()       asm volatile("cp.async.wait_group 1;" ::: "memory")

__device__ __forceinline__ void ldm_x4(uint32_t* r, uint32_t addr) {
    asm volatile("ldmatrix.sync.aligned.m8n8.x4.shared.b16 {%0,%1,%2,%3}, [%4];"
                 : "=r"(r[0]), "=r"(r[1]), "=r"(r[2]), "=r"(r[3]) : "r"(addr));
}
__device__ __forceinline__ void mma_fp16(float* c, const uint32_t* a, const uint32_t* b) {
    asm volatile(
        "mma.sync.aligned.m16n8k16.row.col.f32.f16.f16.f32 "
        "{%0,%1,%2,%3}, {%4,%5,%6,%7}, {%8,%9}, {%0,%1,%2,%3};"
        : "+f"(c[0]), "+f"(c[1]), "+f"(c[2]), "+f"(c[3])
        : "r"(a[0]), "r"(a[1]), "r"(a[2]), "r"(a[3]), "r"(b[0]), "r"(b[1]));
}

// ---------------- weight convert: fp32 -> fp16 (8 elems/thread/iter) ----------------
__global__ void cvt_w_kernel(const float4* __restrict__ W, uint4* __restrict__ O,
                             unsigned total8) {
    unsigned i = blockIdx.x * blockDim.x + threadIdx.x;
    const unsigned stride = gridDim.x * blockDim.x;
    for (; i < total8; i += stride) {
        float4 v0 = W[i * 2];
        float4 v1 = W[i * 2 + 1];
        __half2 h0 = __floats2half2_rn(v0.x, v0.y);
        __half2 h1 = __floats2half2_rn(v0.z, v0.w);
        __half2 h2 = __floats2half2_rn(v1.x, v1.y);
        __half2 h3 = __floats2half2_rn(v1.z, v1.w);
        uint4 o;
        o.x = *(uint32_t*)&h0; o.y = *(uint32_t*)&h1;
        o.z = *(uint32_t*)&h2; o.w = *(uint32_t*)&h3;
        O[i] = o;
    }
}

// ---------------- RMSNorm -> fp16 ----------------
__global__ void rmsnorm_f16_kernel(const float* __restrict__ x,
                                   const float* __restrict__ w,
                                   __half* __restrict__ out) {
    const int row = blockIdx.x;
    const float4* xr = (const float4*)(x + (size_t)row * HID);
    const float4* wv4 = (const float4*)w;

    float4 v[2];
    float ss = 0.f;
#pragma unroll
    for (int i = 0; i < 2; i++) {
        v[i] = xr[threadIdx.x + i * 256];
        ss += v[i].x * v[i].x + v[i].y * v[i].y + v[i].z * v[i].z + v[i].w * v[i].w;
    }
#pragma unroll
    for (int o = 16; o; o >>= 1) ss += __shfl_xor_sync(0xffffffffu, ss, o);
    __shared__ float sred[8];
    if ((threadIdx.x & 31) == 0) sred[threadIdx.x >> 5] = ss;
    __syncthreads();
    if (threadIdx.x < 8) {
        float t = sred[threadIdx.x];
#pragma unroll
        for (int o = 4; o; o >>= 1) t += __shfl_xor_sync(0xffu, t, o);
        if (threadIdx.x == 0) sred[0] = t;
    }
    __syncthreads();
    const float scale = rsqrtf(sred[0] * (1.0f / HID) + 1e-6f);

    uint2* orow = (uint2*)(out + (size_t)row * HID);
#pragma unroll
    for (int i = 0; i < 2; i++) {
        float4 wv = wv4[threadIdx.x + i * 256];
        __half2 h01 = __floats2half2_rn(v[i].x * scale * wv.x, v[i].y * scale * wv.y);
        __half2 h23 = __floats2half2_rn(v[i].z * scale * wv.z, v[i].w * scale * wv.w);
        uint2 o;
        o.x = *(uint32_t*)&h01;
        o.y = *(uint32_t*)&h23;
        orow[threadIdx.x + i * 256] = o;
    }
}

// ---------------- HMMA GEMM: C[m,n] = epi(sum_k A[m,k]*B[n,k]), fp16 ----------------
// CTA tile 128x128, 128 threads (4 warps, 2m x 2n), warp tile 64x64, BK=64.
// 3-stage cp.async pipeline (96KB smem, 2 CTAs/SM), SW128 swizzle,
// ldmatrix double-buffered across kk + mma.m16n8k16.
// EPI: 1 = silu->C(f32) ; 2 = acc*C -> Dst(f16) ; 3 = acc+Res -> C(f32) ; 4 = Dst(f16)
#define NSTAGE 3
#define A_BYTES 16384               // 128 rows * 128B
#define STG     32768               // A 16KB + B 16KB
#define SMEM_TOTAL (NSTAGE * STG)   // 96KB

template <int EPI>
__global__ void __launch_bounds__(128, 2)
gemm_f16(const __half* __restrict__ A, const __half* __restrict__ B,
         float* __restrict__ C, const float* __restrict__ Res,
         __half* __restrict__ Dst, int N, int K) {
    extern __shared__ __align__(1024) char smem[];
    const uint32_t sb = smem_u32(smem);
    const int tid = threadIdx.x;
    const int lane = tid & 31;
    const int w = tid >> 5;
    const int mw = w >> 1;            // 0..1  (64-row slab)
    const int nw = w & 1;             // 0..1  (64-col slab)
    const int bm = blockIdx.y * 128;
    const int bn = blockIdx.x * 128;
    const int nch = K >> 6;           // 64-elem chunks
    const uint32_t strideK = (uint32_t)K;
    const uint32_t rowskip16 = strideK * 32u;   // 16 rows * K halves * 2B

    // ---- loader: 16 x 16B per thread (8 for A, 8 for B); strided form ----
    const char* Abase = (const char*)A;
    const char* Bbase = (const char*)B;
    const int lr = tid >> 3;                    // 0..15  (row within 16-row group)
    const int lc = tid & 7;                     // 0..7   (16B column)
    const uint32_t l_dst0 = (uint32_t)(lr * 128 + ((lc * 16) ^ ((lr & 7) << 4)));
    const uint32_t a_off0 = ((uint32_t)(bm + lr) * strideK + (uint32_t)lc * 8u) * 2u;
    uint32_t b_off[8];
#pragma unroll
    for (int i = 0; i < 8; i++) {
        int gr = bn + lr + 16 * i; if (gr > N - 1) gr = N - 1;
        b_off[i] = ((uint32_t)gr * strideK + (uint32_t)lc * 8u) * 2u;
    }

    auto load_stage = [&](int stage, int ch) {
        const uint32_t co = (uint32_t)ch * 128u;   // 64 halfs = 128 bytes
        uint32_t ab = sb + stage * STG + l_dst0;
        uint32_t bb = ab + A_BYTES;
        const char* ap = Abase + a_off0 + co;
        const char* bp = Bbase + co;
#pragma unroll
        for (int i = 0; i < 8; i++) CP16(ab + (uint32_t)(i * 2048), ap + (size_t)i * rowskip16);
#pragma unroll
        for (int i = 0; i < 8; i++) CP16(bb + (uint32_t)(i * 2048), bp + b_off[i]);
        CP_COMMIT();
    };

    // ---- ldmatrix lane addressing ----
    const int arow = mw * 64 + (lane & 15);
    const uint32_t a_xor = (uint32_t)((arow & 7) << 4);
    const uint32_t a_rb = (uint32_t)(arow * 128);
    const uint32_t a_k0 = (uint32_t)((lane >> 4) * 16);
    const int brow = nw * 64 + ((lane >> 4) & 1) * 8 + (lane & 7);
    const uint32_t b_xor = (uint32_t)((brow & 7) << 4);
    const uint32_t b_rb = (uint32_t)(brow * 128);
    const uint32_t b_k0 = (uint32_t)(((lane >> 3) & 1) * 16);

    float acc[4][8][4];
#pragma unroll
    for (int i = 0; i < 4; i++)
#pragma unroll
        for (int j = 0; j < 8; j++)
#pragma unroll
            for (int q = 0; q < 4; q++) acc[i][j][q] = 0.f;

    uint32_t af[2][4][4], bf[2][4][4];

    // ---- pipeline ----
    load_stage(0, 0);
    load_stage(1, 1);

    for (int s = 0; s < nch; s++) {
        const int stage = s % NSTAGE;
        CP_WAIT1();                   // chunk s resident
        __syncthreads();              // stage (s-1)%3 == (s+2)%3 free for reuse

        const int nc = s + 2;
        if (nc < nch) load_stage(nc % NSTAGE, nc);
        else          CP_COMMIT();    // empty group keeps wait accounting exact

        const uint32_t sA = sb + stage * STG;
        const uint32_t sB = sA + A_BYTES;

        // prime kk=0 fragments
#pragma unroll
        for (int ma = 0; ma < 4; ma++)
            ldm_x4(af[0][ma], sA + a_rb + (uint32_t)(ma * 2048) + (a_k0 ^ a_xor));
#pragma unroll
        for (int nb = 0; nb < 4; nb++)
            ldm_x4(bf[0][nb], sB + b_rb + (uint32_t)(nb * 2048) + (b_k0 ^ b_xor));

#pragma unroll
        for (int kk = 0; kk < 4; kk++) {
            const int cur = kk & 1, nxt = cur ^ 1;
            if (kk < 3) {   // prefetch next kk's fragments under this kk's MMAs
#pragma unroll
                for (int ma = 0; ma < 4; ma++)
                    ldm_x4(af[nxt][ma], sA + a_rb + (uint32_t)(ma * 2048) + (((kk + 1) * 32 + a_k0) ^ a_xor));
#pragma unroll
                for (int nb = 0; nb < 4; nb++)
                    ldm_x4(bf[nxt][nb], sB + b_rb + (uint32_t)(nb * 2048) + (((kk + 1) * 32 + b_k0) ^ b_xor));
            }
#pragma unroll
            for (int ma = 0; ma < 4; ma++)
#pragma unroll
                for (int na = 0; na < 8; na++)
                    mma_fp16(acc[ma][na], af[cur][ma], &bf[cur][na >> 1][(na & 1) * 2]);
        }
    }

    // ---- epilogue ----
#pragma unroll
    for (int ma = 0; ma < 4; ma++) {
        const int gm0 = bm + mw * 64 + ma * 16 + (lane >> 2);
#pragma unroll
        for (int na = 0; na < 8; na++) {
            const int gn = bn + nw * 64 + na * 8 + (lane & 3) * 2;
            if (gn >= N) continue;
            const float* c = acc[ma][na];
#pragma unroll
            for (int h = 0; h < 2; h++) {
                const int gm = gm0 + h * 8;
                float v0 = c[h * 2 + 0], v1 = c[h * 2 + 1];
                if (EPI == 1) {
                    float2 o;
                    o.x = v0 / (1.f + __expf(-v0));
                    o.y = v1 / (1.f + __expf(-v1));
                    *(float2*)(C + (size_t)gm * N + gn) = o;
                } else if (EPI == 2) {
                    float2 g = *(const float2*)(C + (size_t)gm * N + gn);
                    __half2 o = __floats2half2_rn(v0 * g.x, v1 * g.y);
                    *(__half2*)(Dst + (size_t)gm * N + gn) = o;
                } else if (EPI == 3) {
                    float2 rr = *(const float2*)(Res + (size_t)gm * N + gn);
                    float2 o; o.x = v0 + rr.x; o.y = v1 + rr.y;
                    *(float2*)(C + (size_t)gm * N + gn) = o;
                } else {  // EPI == 4
                    __half2 o = __floats2half2_rn(v0, v1);
                    *(__half2*)(Dst + (size_t)gm * N + gn) = o;
                }
            }
        }
    }
}

// ---------------- launch ----------------
extern "C" void kernel_launch(void* const* d_in, const int* in_sizes, int n_in,
                              void* d_out, int out_size) {
    const float* x      = (const float*)d_in[0];
    const float* in_w   = (const float*)d_in[2];
    const float* post_w = (const float*)d_in[3];
    const float* Wq     = (const float*)d_in[4];
    const float* Wo     = (const float*)d_in[5];
    const float* Wg     = (const float*)d_in[6];
    const float* Wu     = (const float*)d_in[7];
    const float* Wd     = (const float*)d_in[8];
    float* out = (float*)d_out;

    __half *w16q, *w16o, *w16g, *w16u, *w16d, *a16h, *a16q, *a16p, *a16m;
    float *hidden, *prodf;
    cudaGetSymbolAddress((void**)&w16q, g_w16q);
    cudaGetSymbolAddress((void**)&w16o, g_w16o);
    cudaGetSymbolAddress((void**)&w16g, g_w16g);
    cudaGetSymbolAddress((void**)&w16u, g_w16u);
    cudaGetSymbolAddress((void**)&w16d, g_w16d);
    cudaGetSymbolAddress((void**)&a16h, g_a16h);
    cudaGetSymbolAddress((void**)&a16q, g_a16q);
    cudaGetSymbolAddress((void**)&a16p, g_a16p);
    cudaGetSymbolAddress((void**)&a16m, g_a16m);
    cudaGetSymbolAddress((void**)&hidden, g_hidden);
    cudaGetSymbolAddress((void**)&prodf, g_prodf);

    cudaFuncSetAttribute(gemm_f16<1>, cudaFuncAttributeMaxDynamicSharedMemorySize, SMEM_TOTAL);
    cudaFuncSetAttribute(gemm_f16<2>, cudaFuncAttributeMaxDynamicSharedMemorySize, SMEM_TOTAL);
    cudaFuncSetAttribute(gemm_f16<3>, cudaFuncAttributeMaxDynamicSharedMemorySize, SMEM_TOTAL);
    cudaFuncSetAttribute(gemm_f16<4>, cudaFuncAttributeMaxDynamicSharedMemorySize, SMEM_TOTAL);

    // weight converts (fp32 -> fp16)
    cvt_w_kernel<<<2048, 256>>>((const float4*)Wq, (uint4*)w16q, (unsigned)((size_t)QD * HID / 8));
    cvt_w_kernel<<<2048, 256>>>((const float4*)Wo, (uint4*)w16o, (unsigned)((size_t)HID * QD / 8));
    cvt_w_kernel<<<2048, 256>>>((const float4*)Wg, (uint4*)w16g, (unsigned)((size_t)INTER_N * HID / 8));
    cvt_w_kernel<<<2048, 256>>>((const float4*)Wu, (uint4*)w16u, (unsigned)((size_t)INTER_N * HID / 8));
    cvt_w_kernel<<<2048, 256>>>((const float4*)Wd, (uint4*)w16d, (unsigned)((size_t)HID * INTER_N / 8));

    const int MT = T_TOK / 128;  // 32

    // 1. input_layernorm -> fp16
    rmsnorm_f16_kernel<<<T_TOK, 256>>>(x, in_w, a16h);
    // 2. q = hnorm @ Wq^T -> fp16
    gemm_f16<4><<<dim3(QD / 128, MT), 128, SMEM_TOTAL>>>(a16h, w16q, nullptr, nullptr, a16q, QD, HID);
    // 3. hidden = x + q @ Wo^T
    gemm_f16<3><<<dim3(HID / 128, MT), 128, SMEM_TOTAL>>>(a16q, w16o, hidden, x, nullptr, HID, QD);
    // 4. post_attention_layernorm -> fp16
    rmsnorm_f16_kernel<<<T_TOK, 256>>>(hidden, post_w, a16p);
    // 5. prodf = silu(hpost @ Wg^T)  (fp32)
    gemm_f16<1><<<dim3((INTER_N + 127) / 128, MT), 128, SMEM_TOTAL>>>(a16p, w16g, prodf, nullptr, nullptr, INTER_N, HID);
    // 6. a16m = fp16(prodf * (hpost @ Wu^T))
    gemm_f16<2><<<dim3((INTER_N + 127) / 128, MT), 128, SMEM_TOTAL>>>(a16p, w16u, prodf, nullptr, a16m, INTER_N, HID);
    // 7. out = hidden + a16m @ Wd^T
    gemm_f16<3><<<dim3(HID / 128, MT), 128, SMEM_TOTAL>>>(a16m, w16d, out, hidden, nullptr, HID, INTER_N);
}